// round 16
// baseline (speedup 1.0000x reference)
#include <cuda_runtime.h>
#include <cuda_fp16.h>
#include <math_constants.h>
#include <cstdint>

#define N_PTS   92160
#define D_DIM   192
#define BD_DIM  256
#define H_HEADS 8
#define FF_DIM  768
#define S_SETS  2560
#define L_LEN   36
#define M_BOX   256
#define HD_DIM  24
#define SPC     4          // sets per attention CTA

// ---------------- scratch (static device globals; no allocation) ----------------
__device__ float g_x[N_PTS * D_DIM];
__device__ float g_k[M_BOX * D_DIM];
__device__ float g_v[M_BOX * D_DIM];
__device__ int   g_fp[N_PTS];

__device__ __half g_qh[N_PTS * D_DIM];
__device__ __half g_ctxh[N_PTS * D_DIM];
__device__ __half g_xh[N_PTS * D_DIM];
__device__ __half g_hh[(size_t)N_PTS * FF_DIM];
__device__ __half g_kh[H_HEADS * M_BOX * 32];      // [h][m][32] padded fp16 K
__device__ __half g_vt[H_HEADS * HD_DIM * M_BOX];  // [h][d][m]  transposed fp16 V
#define WOFF_Q 0
#define WOFF_O 36864
#define WOFF_1 73728
#define WOFF_2 221184
__device__ __half g_wh[368640];

__device__ __forceinline__ void mma16816(float* d, const uint32_t* a, const uint32_t* b) {
    asm volatile(
        "mma.sync.aligned.m16n8k16.row.col.f32.f16.f16.f32 "
        "{%0,%1,%2,%3}, {%4,%5,%6,%7}, {%8,%9}, {%0,%1,%2,%3};\n"
        : "+f"(d[0]), "+f"(d[1]), "+f"(d[2]), "+f"(d[3])
        : "r"(a[0]), "r"(a[1]), "r"(a[2]), "r"(a[3]), "r"(b[0]), "r"(b[1]));
}

__device__ __forceinline__ uint4 add_cvt8(const float* p, const float* q) {
    float4 x0 = *(const float4*)p;
    float4 x1 = *(const float4*)(p + 4);
    float4 y0 = *(const float4*)q;
    float4 y1 = *(const float4*)(q + 4);
    __half2 h0 = __floats2half2_rn(x0.x + y0.x, x0.y + y0.y);
    __half2 h1 = __floats2half2_rn(x0.z + y0.z, x0.w + y0.w);
    __half2 h2 = __floats2half2_rn(x1.x + y1.x, x1.y + y1.y);
    __half2 h3 = __floats2half2_rn(x1.z + y1.z, x1.w + y1.w);
    uint4 r;
    r.x = *(uint32_t*)&h0; r.y = *(uint32_t*)&h1;
    r.z = *(uint32_t*)&h2; r.w = *(uint32_t*)&h3;
    return r;
}

// ================= A-resident fp16 GEMM for K=192: C = A @ W^T + bias =================
#define ARES_SMEM ((128 * 200 + 2 * 64 * 40) * 2)

template<bool RELU, bool OUTH, bool ADDIN, int NTILES>
__global__ __launch_bounds__(256)
void hgemm_ares(const __half* __restrict__ A, const float* __restrict__ Af,
                const float* __restrict__ Af2, const __half* __restrict__ W,
                const float* __restrict__ bias, float* __restrict__ C,
                __half* __restrict__ Ch, int Dout)
{
    extern __shared__ __half dsm[];
    __half* As = dsm;                 // 128 x 200
    __half* Wb0 = dsm + 25600;        // 64 x 40
    __half* Wb1 = dsm + 28160;

    const int tid  = threadIdx.x;
    const int lane = tid & 31;
    const int wid  = tid >> 5;
    const int wm   = wid & 3;
    const int wn   = wid >> 2;
    const int m0   = blockIdx.x * 128;
    const int lr   = lane >> 2;
    const int lc2  = (lane & 3) * 2;

    #pragma unroll
    for (int j = 0; j < 12; j++) {
        const int idx = tid + 256 * j;
        const int r = idx / 24, c8 = (idx % 24) * 8;
        const size_t go = (size_t)(m0 + r) * 192 + c8;
        uint4 v;
        if (ADDIN) v = add_cvt8(Af + go, Af2 + go);
        else       v = *(const uint4*)(A + go);
        *(uint4*)(As + r * 200 + c8) = v;
    }

    const int rw = tid >> 2;
    const int cw = (tid & 3) * 8;
    const int sW = rw * 40 + cw;

    const int NI = NTILES * 6;
    uint4 pw = *(const uint4*)(W + (size_t)rw * 192 + cw);
    *(uint4*)(Wb0 + sW) = pw;

    float acc[2][4][4];

    for (int i = 0; i < NI; ++i) {
        const int nt = i / 6, kc = i % 6;
        __syncthreads();

        if (kc == 0) {
            #pragma unroll
            for (int a = 0; a < 2; a++)
                #pragma unroll
                for (int b = 0; b < 4; b++)
                    #pragma unroll
                    for (int e = 0; e < 4; e++) acc[a][b][e] = 0.f;
        }

        if (i + 1 < NI) {
            const int nt2 = (i + 1) / 6, kc2 = (i + 1) % 6;
            pw = *(const uint4*)(W + (size_t)(nt2 * 64 + rw) * 192 + kc2 * 32 + cw);
        }

        const __half* Ws = (i & 1) ? Wb1 : Wb0;
        const int ca = kc * 32;

        #pragma unroll
        for (int ks = 0; ks < 32; ks += 16) {
            uint32_t af[2][4], bf[4][2];
            #pragma unroll
            for (int a = 0; a < 2; a++) {
                const __half* p = As + (wm * 32 + a * 16 + lr) * 200 + ca + ks + lc2;
                af[a][0] = *(const uint32_t*)(p);
                af[a][1] = *(const uint32_t*)(p + 8 * 200);
                af[a][2] = *(const uint32_t*)(p + 8);
                af[a][3] = *(const uint32_t*)(p + 8 * 200 + 8);
            }
            #pragma unroll
            for (int b = 0; b < 4; b++) {
                const __half* p = Ws + (wn * 32 + b * 8 + lr) * 40 + ks + lc2;
                bf[b][0] = *(const uint32_t*)(p);
                bf[b][1] = *(const uint32_t*)(p + 8);
            }
            #pragma unroll
            for (int a = 0; a < 2; a++)
                #pragma unroll
                for (int b = 0; b < 4; b++)
                    mma16816(acc[a][b], af[a], bf[b]);
        }

        if (kc == 5) {
            const int n0 = nt * 64;
            #pragma unroll
            for (int a = 0; a < 2; a++) {
                const int r = m0 + wm * 32 + a * 16 + lr;
                #pragma unroll
                for (int b = 0; b < 4; b++) {
                    const int cj = n0 + wn * 32 + b * 8 + lc2;
                    const float2 bx = *(const float2*)(bias + cj);
                    float v0 = acc[a][b][0] + bx.x;
                    float v1 = acc[a][b][1] + bx.y;
                    float v2 = acc[a][b][2] + bx.x;
                    float v3 = acc[a][b][3] + bx.y;
                    if (RELU) {
                        v0 = fmaxf(v0, 0.f); v1 = fmaxf(v1, 0.f);
                        v2 = fmaxf(v2, 0.f); v3 = fmaxf(v3, 0.f);
                    }
                    if (OUTH) {
                        *(__half2*)(Ch + (size_t)r       * Dout + cj) = __floats2half2_rn(v0, v1);
                        *(__half2*)(Ch + (size_t)(r + 8) * Dout + cj) = __floats2half2_rn(v2, v3);
                    } else {
                        *(float2*)(C + (size_t)r       * Dout + cj) = make_float2(v0, v1);
                        *(float2*)(C + (size_t)(r + 8) * Dout + cj) = make_float2(v2, v3);
                    }
                }
            }
        }

        if (i + 1 < NI) {
            __half* nb = ((i + 1) & 1) ? Wb1 : Wb0;
            *(uint4*)(nb + sW) = pw;
        }
    }
}

// ================= wide fp16 GEMM core (BN=192) with two fused-LN epilogues ==========
#define WIDE_SMEM (2 * 320 * 40 * 2)   // 51200 B

// FFN2 + LN2: out = LN(X + A@W^T + bias)       (K = 768)
__global__ __launch_bounds__(256)
void hgemm_wide_ln(const __half* __restrict__ A, const __half* __restrict__ W,
                   const float* __restrict__ bias, const float* __restrict__ X,
                   const float* __restrict__ gamma, const float* __restrict__ beta,
                   float* __restrict__ Out)
{
    extern __shared__ __half wsm[];
    const int K = FF_DIM;
    const int Dout = D_DIM;

    const int tid  = threadIdx.x;
    const int lane = tid & 31;
    const int wid  = tid >> 5;
    const int wm   = wid & 3;
    const int wn   = wid >> 2;
    const int m0   = blockIdx.x * 128;
    const int lr   = lane >> 2;
    const int lc2  = (lane & 3) * 2;

    const int nT = K >> 5;

    int lrow[5], lcol[5];
    const __half* gptr[5];
    #pragma unroll
    for (int j = 0; j < 5; j++) {
        const int u = tid + 256 * j;
        const int r = u >> 2, c8 = (u & 3) * 8;
        lrow[j] = r; lcol[j] = c8;
        gptr[j] = (r < 128) ? (A + (size_t)(m0 + r) * K + c8)
                            : (W + (size_t)(r - 128) * K + c8);
    }

    uint4 st[5];
    #pragma unroll
    for (int j = 0; j < 5; j++) st[j] = *(const uint4*)(gptr[j]);

    float acc[2][12][4];
    #pragma unroll
    for (int a = 0; a < 2; a++)
        #pragma unroll
        for (int b = 0; b < 12; b++)
            #pragma unroll
            for (int e = 0; e < 4; e++) acc[a][b][e] = 0.f;

    {
        __half* s0 = wsm;
        #pragma unroll
        for (int j = 0; j < 5; j++)
            *(uint4*)(s0 + lrow[j] * 40 + lcol[j]) = st[j];
    }

    for (int t = 0; t < nT; ++t) {
        __syncthreads();

        if (t + 1 < nT) {
            const int off = (t + 1) * 32;
            #pragma unroll
            for (int j = 0; j < 5; j++) st[j] = *(const uint4*)(gptr[j] + off);
        }

        const __half* As = wsm + (t & 1) * (320 * 40);
        const __half* Ws = As + 128 * 40;

        #pragma unroll
        for (int ks = 0; ks < 32; ks += 16) {
            uint32_t af[2][4];
            #pragma unroll
            for (int a = 0; a < 2; a++) {
                const __half* p = As + (wm * 32 + a * 16 + lr) * 40 + ks + lc2;
                af[a][0] = *(const uint32_t*)(p);
                af[a][1] = *(const uint32_t*)(p + 8 * 40);
                af[a][2] = *(const uint32_t*)(p + 8);
                af[a][3] = *(const uint32_t*)(p + 8 * 40 + 8);
            }
            #pragma unroll
            for (int b = 0; b < 12; b++) {
                uint32_t bf[2];
                const __half* p = Ws + (wn * 96 + b * 8 + lr) * 40 + ks + lc2;
                bf[0] = *(const uint32_t*)(p);
                bf[1] = *(const uint32_t*)(p + 8);
                mma16816(acc[0][b], af[0], bf);
                mma16816(acc[1][b], af[1], bf);
            }
        }

        if (t + 1 < nT) {
            __half* nb = wsm + ((t + 1) & 1) * (320 * 40);
            #pragma unroll
            for (int j = 0; j < 5; j++)
                *(uint4*)(nb + lrow[j] * 40 + lcol[j]) = st[j];
        }
    }

    __syncthreads();
    float* redsum = (float*)wsm;
    float* redsq  = redsum + 1024;
    float* stats  = redsq + 1024;

    const int part = wn * 4 + (lane & 3);

    #pragma unroll
    for (int a = 0; a < 2; a++) {
        #pragma unroll
        for (int hf = 0; hf < 2; hf++) {
            const int rl = wm * 32 + a * 16 + hf * 8 + lr;
            const int r  = m0 + rl;
            float s = 0.f, q = 0.f;
            #pragma unroll
            for (int b = 0; b < 12; b++) {
                const int cj = wn * 96 + b * 8 + lc2;
                const float2 bx = *(const float2*)(bias + cj);
                const float2 xv = *(const float2*)(X + (size_t)r * Dout + cj);
                float v0 = acc[a][b][hf*2+0] + bx.x + xv.x;
                float v1 = acc[a][b][hf*2+1] + bx.y + xv.y;
                acc[a][b][hf*2+0] = v0;
                acc[a][b][hf*2+1] = v1;
                s += v0 + v1;
                q += v0 * v0 + v1 * v1;
            }
            redsum[rl * 8 + part] = s;
            redsq [rl * 8 + part] = q;
        }
    }
    __syncthreads();

    if (tid < 128) {
        float s = 0.f, q = 0.f;
        #pragma unroll
        for (int p = 0; p < 8; p++) { s += redsum[tid * 8 + p]; q += redsq[tid * 8 + p]; }
        const float mean = s * (1.0f / D_DIM);
        const float var  = q * (1.0f / D_DIM) - mean * mean;
        stats[tid * 2]     = mean;
        stats[tid * 2 + 1] = rsqrtf(var + 1e-5f);
    }
    __syncthreads();

    #pragma unroll
    for (int a = 0; a < 2; a++) {
        #pragma unroll
        for (int hf = 0; hf < 2; hf++) {
            const int rl = wm * 32 + a * 16 + hf * 8 + lr;
            const int r  = m0 + rl;
            const float mean = stats[rl * 2];
            const float inv  = stats[rl * 2 + 1];
            #pragma unroll
            for (int b = 0; b < 12; b++) {
                const int cj = wn * 96 + b * 8 + lc2;
                const float2 gg = *(const float2*)(gamma + cj);
                const float2 bb2 = *(const float2*)(beta + cj);
                const float v0 = acc[a][b][hf*2+0];
                const float v1 = acc[a][b][hf*2+1];
                *(float2*)(Out + (size_t)r * Dout + cj) =
                    make_float2((v0 - mean) * inv * gg.x + bb2.x,
                                (v1 - mean) * inv * gg.y + bb2.y);
            }
        }
    }
}

// O-proj + gather + LN1: for proj row r, n = vinds[r]; if fp[n]==r:
//   x[n] = LN(src[n] + proj_r + bias), also half copy xh[n].   (K = 192)
__global__ __launch_bounds__(256)
void hgemm_wide_gln(const __half* __restrict__ A, const __half* __restrict__ W,
                    const float* __restrict__ bias, const float* __restrict__ src,
                    const int* __restrict__ vinds, const int* __restrict__ fp,
                    const float* __restrict__ gamma, const float* __restrict__ beta,
                    float* __restrict__ OutX, __half* __restrict__ OutXh)
{
    extern __shared__ __half wsm[];
    const int K = D_DIM;               // 192
    const int Dout = D_DIM;

    const int tid  = threadIdx.x;
    const int lane = tid & 31;
    const int wid  = tid >> 5;
    const int wm   = wid & 3;
    const int wn   = wid >> 2;
    const int m0   = blockIdx.x * 128;
    const int lr   = lane >> 2;
    const int lc2  = (lane & 3) * 2;

    const int nT = K >> 5;             // 6

    int lrow[5], lcol[5];
    const __half* gptr[5];
    #pragma unroll
    for (int j = 0; j < 5; j++) {
        const int u = tid + 256 * j;
        const int r = u >> 2, c8 = (u & 3) * 8;
        lrow[j] = r; lcol[j] = c8;
        gptr[j] = (r < 128) ? (A + (size_t)(m0 + r) * K + c8)
                            : (W + (size_t)(r - 128) * K + c8);
    }

    uint4 st[5];
    #pragma unroll
    for (int j = 0; j < 5; j++) st[j] = *(const uint4*)(gptr[j]);

    float acc[2][12][4];
    #pragma unroll
    for (int a = 0; a < 2; a++)
        #pragma unroll
        for (int b = 0; b < 12; b++)
            #pragma unroll
            for (int e = 0; e < 4; e++) acc[a][b][e] = 0.f;

    {
        __half* s0 = wsm;
        #pragma unroll
        for (int j = 0; j < 5; j++)
            *(uint4*)(s0 + lrow[j] * 40 + lcol[j]) = st[j];
    }

    for (int t = 0; t < nT; ++t) {
        __syncthreads();

        if (t + 1 < nT) {
            const int off = (t + 1) * 32;
            #pragma unroll
            for (int j = 0; j < 5; j++) st[j] = *(const uint4*)(gptr[j] + off);
        }

        const __half* As = wsm + (t & 1) * (320 * 40);
        const __half* Ws = As + 128 * 40;

        #pragma unroll
        for (int ks = 0; ks < 32; ks += 16) {
            uint32_t af[2][4];
            #pragma unroll
            for (int a = 0; a < 2; a++) {
                const __half* p = As + (wm * 32 + a * 16 + lr) * 40 + ks + lc2;
                af[a][0] = *(const uint32_t*)(p);
                af[a][1] = *(const uint32_t*)(p + 8 * 40);
                af[a][2] = *(const uint32_t*)(p + 8);
                af[a][3] = *(const uint32_t*)(p + 8 * 40 + 8);
            }
            #pragma unroll
            for (int b = 0; b < 12; b++) {
                uint32_t bf[2];
                const __half* p = Ws + (wn * 96 + b * 8 + lr) * 40 + ks + lc2;
                bf[0] = *(const uint32_t*)(p);
                bf[1] = *(const uint32_t*)(p + 8);
                mma16816(acc[0][b], af[0], bf);
                mma16816(acc[1][b], af[1], bf);
            }
        }

        if (t + 1 < nT) {
            __half* nb = wsm + ((t + 1) & 1) * (320 * 40);
            #pragma unroll
            for (int j = 0; j < 5; j++)
                *(uint4*)(nb + lrow[j] * 40 + lcol[j]) = st[j];
        }
    }

    // ---- fused epilogue: gather target row, residual, LN, conditional write ----
    __syncthreads();
    float* redsum = (float*)wsm;
    float* redsq  = redsum + 1024;
    float* stats  = redsq + 1024;

    const int part = wn * 4 + (lane & 3);

    int nrow[2][2];
    bool valid[2][2];

    #pragma unroll
    for (int a = 0; a < 2; a++) {
        #pragma unroll
        for (int hf = 0; hf < 2; hf++) {
            const int rl = wm * 32 + a * 16 + hf * 8 + lr;
            const int r  = m0 + rl;
            int n = vinds[r];
            if (n < 0 || n >= N_PTS) n = 0;
            nrow[a][hf]  = n;
            valid[a][hf] = (fp[n] == r);
            float s = 0.f, q = 0.f;
            #pragma unroll
            for (int b = 0; b < 12; b++) {
                const int cj = wn * 96 + b * 8 + lc2;
                const float2 bx = *(const float2*)(bias + cj);
                const float2 xv = *(const float2*)(src + (size_t)n * Dout + cj);
                float v0 = acc[a][b][hf*2+0] + bx.x + xv.x;
                float v1 = acc[a][b][hf*2+1] + bx.y + xv.y;
                acc[a][b][hf*2+0] = v0;
                acc[a][b][hf*2+1] = v1;
                s += v0 + v1;
                q += v0 * v0 + v1 * v1;
            }
            redsum[rl * 8 + part] = s;
            redsq [rl * 8 + part] = q;
        }
    }
    __syncthreads();

    if (tid < 128) {
        float s = 0.f, q = 0.f;
        #pragma unroll
        for (int p = 0; p < 8; p++) { s += redsum[tid * 8 + p]; q += redsq[tid * 8 + p]; }
        const float mean = s * (1.0f / D_DIM);
        const float var  = q * (1.0f / D_DIM) - mean * mean;
        stats[tid * 2]     = mean;
        stats[tid * 2 + 1] = rsqrtf(var + 1e-5f);
    }
    __syncthreads();

    #pragma unroll
    for (int a = 0; a < 2; a++) {
        #pragma unroll
        for (int hf = 0; hf < 2; hf++) {
            const int rl = wm * 32 + a * 16 + hf * 8 + lr;
            if (!valid[a][hf]) continue;
            const int n = nrow[a][hf];
            const float mean = stats[rl * 2];
            const float inv  = stats[rl * 2 + 1];
            #pragma unroll
            for (int b = 0; b < 12; b++) {
                const int cj = wn * 96 + b * 8 + lc2;
                const float2 gg  = *(const float2*)(gamma + cj);
                const float2 bb2 = *(const float2*)(beta + cj);
                const float v0 = (acc[a][b][hf*2+0] - mean) * inv * gg.x + bb2.x;
                const float v1 = (acc[a][b][hf*2+1] - mean) * inv * gg.y + bb2.y;
                *(float2*)(OutX + (size_t)n * Dout + cj) = make_float2(v0, v1);
                *(__half2*)(OutXh + (size_t)n * Dout + cj) = __floats2half2_rn(v0, v1);
            }
        }
    }
}

// ---------------- combined K/V projection (SIMT fp32), blockIdx.z selects ----------------
#define BM 128
#define BN 64
#define BK 16

__global__ __launch_bounds__(256, 2)
void gemm_kv(const float* __restrict__ boxf, const float* __restrict__ boxp,
             const float* __restrict__ Wk, const float* __restrict__ bk, float* __restrict__ Ck,
             const float* __restrict__ Wv, const float* __restrict__ bv, float* __restrict__ Cv)
{
    const bool isK = (blockIdx.z == 0);
    const float* A   = boxf;
    const float* A2  = isK ? boxp : nullptr;
    const float* W   = isK ? Wk : Wv;
    const float* bias= isK ? bk : bv;
    float* C         = isK ? Ck : Cv;
    const int K = BD_DIM, Dout = D_DIM;

    __shared__ float As[BK][BM + 4];
    __shared__ float Ws[BK][BN + 4];

    const int tid = threadIdx.x;
    const int tx = tid & 15;
    const int ty = tid >> 4;
    const int m0 = blockIdx.y * BM;
    const int n0 = blockIdx.x * BN;

    const int ar = tid >> 2;
    const int ac = (tid & 3) << 2;

    const float* Ap0 = A + (size_t)(m0 + ar)      * K + ac;
    const float* Ap1 = A + (size_t)(m0 + ar + 64) * K + ac;
    const float* Wp  = W + (size_t)(n0 + ar)      * K + ac;

    const int nT = K / BK;

    float4 pa0 = *(const float4*)(Ap0);
    float4 pa1 = *(const float4*)(Ap1);
    float4 pw  = *(const float4*)(Wp);
    if (isK) {
        const float* B0 = A2 + (size_t)(m0 + ar) * K + ac;
        const float* B1 = A2 + (size_t)(m0 + ar + 64) * K + ac;
        float4 q0 = *(const float4*)B0;
        float4 q1 = *(const float4*)B1;
        pa0.x += q0.x; pa0.y += q0.y; pa0.z += q0.z; pa0.w += q0.w;
        pa1.x += q1.x; pa1.y += q1.y; pa1.z += q1.z; pa1.w += q1.w;
    }

    float acc[8][4];
    #pragma unroll
    for (int i = 0; i < 8; i++)
        #pragma unroll
        for (int j = 0; j < 4; j++) acc[i][j] = 0.f;

    for (int t = 0; t < nT; ++t) {
        As[ac+0][ar]    = pa0.x; As[ac+1][ar]    = pa0.y;
        As[ac+2][ar]    = pa0.z; As[ac+3][ar]    = pa0.w;
        As[ac+0][ar+64] = pa1.x; As[ac+1][ar+64] = pa1.y;
        As[ac+2][ar+64] = pa1.z; As[ac+3][ar+64] = pa1.w;
        Ws[ac+0][ar]    = pw.x;  Ws[ac+1][ar]    = pw.y;
        Ws[ac+2][ar]    = pw.z;  Ws[ac+3][ar]    = pw.w;
        __syncthreads();

        if (t + 1 < nT) {
            const int off = (t + 1) * BK;
            pa0 = *(const float4*)(Ap0 + off);
            pa1 = *(const float4*)(Ap1 + off);
            pw  = *(const float4*)(Wp  + off);
            if (isK) {
                const float* B0 = A2 + (size_t)(m0 + ar) * K + ac + off;
                const float* B1 = A2 + (size_t)(m0 + ar + 64) * K + ac + off;
                float4 q0 = *(const float4*)B0;
                float4 q1 = *(const float4*)B1;
                pa0.x += q0.x; pa0.y += q0.y; pa0.z += q0.z; pa0.w += q0.w;
                pa1.x += q1.x; pa1.y += q1.y; pa1.z += q1.z; pa1.w += q1.w;
            }
        }

        #pragma unroll
        for (int k = 0; k < BK; ++k) {
            float a[8], w[4];
            #pragma unroll
            for (int i = 0; i < 8; i++) a[i] = As[k][ty * 8 + i];
            #pragma unroll
            for (int j = 0; j < 4; j++) w[j] = Ws[k][tx * 4 + j];
            #pragma unroll
            for (int i = 0; i < 8; i++)
                #pragma unroll
                for (int j = 0; j < 4; j++) acc[i][j] += a[i] * w[j];
        }
        __syncthreads();
    }

    const float b0 = bias[n0 + tx*4 + 0];
    const float b1 = bias[n0 + tx*4 + 1];
    const float b2 = bias[n0 + tx*4 + 2];
    const float b3 = bias[n0 + tx*4 + 3];
    #pragma unroll
    for (int i = 0; i < 8; i++) {
        float4 o;
        o.x = acc[i][0] + b0; o.y = acc[i][1] + b1;
        o.z = acc[i][2] + b2; o.w = acc[i][3] + b3;
        *(float4*)(C + (size_t)(m0 + ty*8 + i) * Dout + n0 + tx*4) = o;
    }
}

// ---------------- K/V pack ----------------
__global__ void kv_pack(const float* __restrict__ kb, const float* __restrict__ vb,
                        __half* __restrict__ khg, __half* __restrict__ vtg)
{
    const int i = blockIdx.x * 256 + threadIdx.x;
    if (i >= H_HEADS * M_BOX) return;
    const int h = i >> 8, m = i & 255;

    {
        const float4* kp = (const float4*)(kb + (size_t)m * D_DIM + h * HD_DIM);
        __half2 hrow[16];
        #pragma unroll
        for (int j = 0; j < 6; j++) {
            float4 f = kp[j];
            hrow[2*j]   = __floats2half2_rn(f.x, f.y);
            hrow[2*j+1] = __floats2half2_rn(f.z, f.w);
        }
        const __half2 zz = __floats2half2_rn(0.f, 0.f);
        hrow[12] = zz; hrow[13] = zz; hrow[14] = zz; hrow[15] = zz;
        uint4* dst = (uint4*)(khg + ((size_t)h * M_BOX + m) * 32);
        dst[0] = ((const uint4*)hrow)[0];
        dst[1] = ((const uint4*)hrow)[1];
        dst[2] = ((const uint4*)hrow)[2];
        dst[3] = ((const uint4*)hrow)[3];
    }
    {
        const float4* vp = (const float4*)(vb + (size_t)m * D_DIM + h * HD_DIM);
        __half* base = vtg + (size_t)h * HD_DIM * M_BOX + m;
        #pragma unroll
        for (int j = 0; j < 6; j++) {
            float4 g = vp[j];
            base[(4*j+0) * M_BOX] = __float2half(g.x);
            base[(4*j+1) * M_BOX] = __float2half(g.y);
            base[(4*j+2) * M_BOX] = __float2half(g.z);
            base[(4*j+3) * M_BOX] = __float2half(g.w);
        }
    }
}

// ================= tensor-core attention: one CTA per (4 sets, head) =================
#define AT_QS   0
#define AT_KS   1920
#define AT_VT   12160
#define AT_PS   18496
#define AT_INT  31168
#define ATTN_SMEM (31168 * 2 + (36 + 256) * 4)

__global__ __launch_bounds__(256)
void attn_mma(const __half* __restrict__ qh, const __half* __restrict__ khg,
              const __half* __restrict__ vtg, const int* __restrict__ vinds,
              const int* __restrict__ vcoords, const int* __restrict__ bcoords,
              __half* __restrict__ ctxh)
{
    extern __shared__ __half sm[];
    __half* Qs = sm + AT_QS;
    __half* Ks = sm + AT_KS;
    __half* Vt = sm + AT_VT;
    __half* Ps = sm + AT_PS;
    int* qb = (int*)(sm + AT_INT);
    int* bb = qb + 36;

    const int s0idx = blockIdx.x * SPC, h = blockIdx.y;
    const int t = threadIdx.x, lane = t & 31, wid = t >> 5;
    const int lr = lane >> 2, lc2 = (lane & 3) * 2;

    {
        const uint4* kp = (const uint4*)(khg + ((size_t)h * M_BOX + t) * 32);
        uint4* krow = (uint4*)(Ks + t * 40);
        krow[0] = kp[0];
        krow[1] = kp[1];
        krow[2] = kp[2];
        krow[3] = kp[3];
        bb[t] = bcoords[t * 4];
    }
    {
        const __half* vsrc = vtg + (size_t)h * HD_DIM * M_BOX;
        #pragma unroll
        for (int j = 0; j < 3; j++) {
            const int idx = t + 256 * j;
            const int r = idx >> 5, c = idx & 31;
            *(uint4*)(Vt + r * 264 + c * 8) = *(const uint4*)(vsrc + r * M_BOX + c * 8);
        }
    }

    for (int si = 0; si < SPC; ++si) {
        const int s = s0idx + si;

        {
            const uint4 z4 = make_uint4(0u, 0u, 0u, 0u);
            for (int i = t; i < 36 * 4; i += 256) {
                const int l = i >> 2, c = i & 3;
                uint4 v;
                if (c < 3) v = *(const uint4*)(qh + (size_t)vinds[s * L_LEN + l] * D_DIM + h * HD_DIM + c * 8);
                else       v = z4;
                *(uint4*)(Qs + l * 40 + c * 8) = v;
            }
        }
        if (t < 36) qb[t] = vcoords[(size_t)vinds[s * L_LEN + t] * 4];
        __syncthreads();

        float acc[3][4][4];
        #pragma unroll
        for (int i = 0; i < 3; i++)
            #pragma unroll
            for (int j = 0; j < 4; j++)
                #pragma unroll
                for (int e = 0; e < 4; e++) acc[i][j][e] = 0.f;

        #pragma unroll
        for (int kk = 0; kk < 2; kk++) {
            const int k0 = kk * 16;
            uint32_t af[3][4], bf[4][2];
            #pragma unroll
            for (int i = 0; i < 3; i++) {
                const __half* p = Qs + (i * 16 + lr) * 40 + k0 + lc2;
                af[i][0] = *(const uint32_t*)(p);
                af[i][1] = *(const uint32_t*)(p + 8 * 40);
                af[i][2] = *(const uint32_t*)(p + 8);
                af[i][3] = *(const uint32_t*)(p + 8 * 40 + 8);
            }
            #pragma unroll
            for (int j = 0; j < 4; j++) {
                const __half* p = Ks + (wid * 32 + j * 8 + lr) * 40 + k0 + lc2;
                bf[j][0] = *(const uint32_t*)(p);
                bf[j][1] = *(const uint32_t*)(p + 8);
            }
            #pragma unroll
            for (int i = 0; i < 3; i++)
                #pragma unroll
                for (int j = 0; j < 4; j++)
                    mma16816(acc[i][j], af[i], bf[j]);
        }

        {
            const float scale = 0.20412414523193154f;
            #pragma unroll
            for (int i = 0; i < 3; i++) {
                const int r0 = i * 16 + lr, r1 = r0 + 8;
                const int q0 = (r0 < L_LEN) ? qb[r0] : 0;
                const int q1 = (r1 < L_LEN) ? qb[r1] : 0;
                #pragma unroll
                for (int j = 0; j < 4; j++) {
                    const int c = wid * 32 + j * 8 + lc2;
                    const int b0 = bb[c], b1 = bb[c + 1];
                    if (r0 < L_LEN) {
                        float v0 = (q0 != b0) ? -CUDART_INF_F : acc[i][j][0] * scale;
                        float v1 = (q0 != b1) ? -CUDART_INF_F : acc[i][j][1] * scale;
                        *(__half2*)(Ps + r0 * 264 + c) = __floats2half2_rn(v0, v1);
                    }
                    if (r1 < L_LEN) {
                        float v2 = (q1 != b0) ? -CUDART_INF_F : acc[i][j][2] * scale;
                        float v3 = (q1 != b1) ? -CUDART_INF_F : acc[i][j][3] * scale;
                        *(__half2*)(Ps + r1 * 264 + c) = __floats2half2_rn(v2, v3);
                    }
                }
            }
        }
        __syncthreads();

        for (int l = wid; l < L_LEN; l += 8) {
            __half* row = Ps + l * 264;
            float e[8];
            float mx = -CUDART_INF_F;
            #pragma unroll
            for (int i = 0; i < 8; i++) { e[i] = __half2float(row[lane + 32*i]); mx = fmaxf(mx, e[i]); }
            #pragma unroll
            for (int o = 16; o > 0; o >>= 1) mx = fmaxf(mx, __shfl_xor_sync(0xffffffffu, mx, o));
            float sum = 0.f;
            if (mx > -CUDART_INF_F) {
                #pragma unroll
                for (int i = 0; i < 8; i++) { e[i] = __expf(e[i] - mx); sum += e[i]; }
            } else {
                #pragma unroll
                for (int i = 0; i < 8; i++) e[i] = 0.f;
            }
            #pragma unroll
            for (int o = 16; o > 0; o >>= 1) sum += __shfl_xor_sync(0xffffffffu, sum, o);
            const float inv = sum > 0.f ? 1.0f / sum : 0.f;
            #pragma unroll
            for (int i = 0; i < 8; i++) row[lane + 32*i] = __float2half(e[i] * inv);
        }
        __syncthreads();

        if (wid < 3) {
            const int mt = wid;
            float a2[3][4];
            #pragma unroll
            for (int n = 0; n < 3; n++)
                #pragma unroll
                for (int e = 0; e < 4; e++) a2[n][e] = 0.f;

            #pragma unroll 4
            for (int kt = 0; kt < 16; kt++) {
                uint32_t af[4];
                const __half* pa = Ps + (mt * 16 + lr) * 264 + kt * 16 + lc2;
                af[0] = *(const uint32_t*)(pa);
                af[1] = *(const uint32_t*)(pa + 8 * 264);
                af[2] = *(const uint32_t*)(pa + 8);
                af[3] = *(const uint32_t*)(pa + 8 * 264 + 8);
                #pragma unroll
                for (int nt = 0; nt < 3; nt++) {
                    uint32_t bf[2];
                    const __half* pb = Vt + (nt * 8 + lr) * 264 + kt * 16 + lc2;
                    bf[0] = *(const uint32_t*)(pb);
                    bf[1] = *(const uint32_t*)(pb + 8);
                    mma16816(a2[nt], af, bf);
                }
            }

            const int r0 = mt * 16 + lr, r1 = r0 + 8;
            #pragma unroll
            for (int nt = 0; nt < 3; nt++) {
                const int c = nt * 8 + lc2;
                if (r0 < L_LEN)
                    *(__half2*)(ctxh + ((size_t)s * L_LEN + r0) * D_DIM + h * HD_DIM + c) = __floats2half2_rn(a2[nt][0], a2[nt][1]);
                if (r1 < L_LEN)
                    *(__half2*)(ctxh + ((size_t)s * L_LEN + r1) * D_DIM + h * HD_DIM + c) = __floats2half2_rn(a2[nt][2], a2[nt][3]);
            }
        }
    }
}

// ---------------- first-occurrence scatter index ----------------
__global__ void init_fp_kernel(int* __restrict__ fp)
{
    int i = blockIdx.x * blockDim.x + threadIdx.x;
    if (i < N_PTS) fp[i] = 0x7FFFFFFF;
}

__global__ void fill_fp_kernel(const int* __restrict__ vinds, int* __restrict__ fp)
{
    int p = blockIdx.x * blockDim.x + threadIdx.x;
    if (p < S_SETS * L_LEN) {
        int n = vinds[p];
        if (n >= 0 && n < N_PTS) atomicMin(&fp[n], p);
    }
}

// ---------------- weight conversion (all four in one launch) ----------------
__global__ void cvt_weights_kernel(const float* __restrict__ Wq, const float* __restrict__ Wo,
                                   const float* __restrict__ W1, const float* __restrict__ W2,
                                   __half* __restrict__ wh)
{
    const int i = blockIdx.x * blockDim.x + threadIdx.x;
    const int n4 = 368640 / 4;
    if (i >= n4) return;
    const int e = i * 4;
    const float* srcp;
    int off;
    if (e < WOFF_O)      { srcp = Wq; off = e - WOFF_Q; }
    else if (e < WOFF_1) { srcp = Wo; off = e - WOFF_O; }
    else if (e < WOFF_2) { srcp = W1; off = e - WOFF_1; }
    else                 { srcp = W2; off = e - WOFF_2; }
    float4 x = *(const float4*)(srcp + off);
    ((__half2*)wh)[2*i]   = __floats2half2_rn(x.x, x.y);
    ((__half2*)wh)[2*i+1] = __floats2half2_rn(x.z, x.w);
}

// ---------------- launch ----------------
extern "C" void kernel_launch(void* const* d_in, const int* in_sizes, int n_in,
                              void* d_out, int out_size)
{
    const float* src     = (const float*)d_in[0];
    const float* pos     = (const float*)d_in[1];
    const float* boxf    = (const float*)d_in[2];
    const float* boxp    = (const float*)d_in[3];
    const int*   vcoords = (const int*)  d_in[4];
    const int*   bcoords = (const int*)  d_in[5];
    const int*   vinds   = (const int*)  d_in[6];
    const float* Wq = (const float*)d_in[7];  const float* bq  = (const float*)d_in[8];
    const float* Wk = (const float*)d_in[9];  const float* bk  = (const float*)d_in[10];
    const float* Wv = (const float*)d_in[11]; const float* bv  = (const float*)d_in[12];
    const float* Wo = (const float*)d_in[13]; const float* bo  = (const float*)d_in[14];
    const float* W1 = (const float*)d_in[15]; const float* b1  = (const float*)d_in[16];
    const float* W2 = (const float*)d_in[17]; const float* b2  = (const float*)d_in[18];
    const float* g1 = (const float*)d_in[19]; const float* be1 = (const float*)d_in[20];
    const float* g2 = (const float*)d_in[21]; const float* be2 = (const float*)d_in[22];
    float* out = (float*)d_out;

    float *xb, *kb, *vb;
    int* fpb;
    __half *qh, *ctxh, *xh, *hh, *wh, *khg, *vtg;
    cudaGetSymbolAddress((void**)&xb,    g_x);
    cudaGetSymbolAddress((void**)&kb,    g_k);
    cudaGetSymbolAddress((void**)&vb,    g_v);
    cudaGetSymbolAddress((void**)&fpb,   g_fp);
    cudaGetSymbolAddress((void**)&qh,    g_qh);
    cudaGetSymbolAddress((void**)&ctxh,  g_ctxh);
    cudaGetSymbolAddress((void**)&xh,    g_xh);
    cudaGetSymbolAddress((void**)&hh,    g_hh);
    cudaGetSymbolAddress((void**)&wh,    g_wh);
    cudaGetSymbolAddress((void**)&khg,   g_kh);
    cudaGetSymbolAddress((void**)&vtg,   g_vt);

    cudaFuncSetAttribute(attn_mma, cudaFuncAttributeMaxDynamicSharedMemorySize, ATTN_SMEM);
    cudaFuncSetAttribute(hgemm_ares<false, true,  true,  3>,  cudaFuncAttributeMaxDynamicSharedMemorySize, ARES_SMEM);
    cudaFuncSetAttribute(hgemm_ares<true,  true,  false, 12>, cudaFuncAttributeMaxDynamicSharedMemorySize, ARES_SMEM);
    cudaFuncSetAttribute(hgemm_wide_ln,  cudaFuncAttributeMaxDynamicSharedMemorySize, WIDE_SMEM);
    cudaFuncSetAttribute(hgemm_wide_gln, cudaFuncAttributeMaxDynamicSharedMemorySize, WIDE_SMEM);

    const int MB = N_PTS / 128;   // 720

    // 1: weight conversion
    cvt_weights_kernel<<<(368640/4 + 255)/256, 256>>>(Wq, Wo, W1, W2, wh);
    // 2: K/V projections
    gemm_kv<<<dim3(D_DIM/BN, M_BOX/BM, 2), 256>>>(boxf, boxp, Wk, bk, kb, Wv, bv, vb);
    // 3: pack K/V into attention-ready fp16 layouts
    kv_pack<<<(H_HEADS * M_BOX) / 256, 256>>>(kb, vb, khg, vtg);
    // 4,5: first-occurrence scatter index (needed by fused O-proj epilogue)
    init_fp_kernel<<<N_PTS / 256, 256>>>(fpb);
    fill_fp_kernel<<<(S_SETS * L_LEN) / 256, 256>>>(vinds, fpb);
    // 6: Q = (src + pos) @ Wq^T + bq  (A-resident, fused add+cvt, HALF output)
    hgemm_ares<false, true, true, 3><<<MB, 256, ARES_SMEM>>>(nullptr, src, pos, wh + WOFF_Q, bq, nullptr, qh, D_DIM);
    // 7: tensor-core masked attention (4 sets per CTA)
    attn_mma<<<dim3(S_SETS / SPC, H_HEADS), 256, ATTN_SMEM>>>(qh, khg, vtg, vinds, vcoords, bcoords, ctxh);
    // 8: O-proj + gather + residual + LN1 fused -> x (fp32) and xh (half)
    hgemm_wide_gln<<<MB, 256, WIDE_SMEM>>>(ctxh, wh + WOFF_O, bo, src, vinds, fpb, g1, be1, xb, xh);
    // 9: FFN1 (A-resident, relu, half out)
    hgemm_ares<true, true, false, 12><<<MB, 256, ARES_SMEM>>>(xh, nullptr, nullptr, wh + WOFF_1, b1, nullptr, hh, FF_DIM);
    // 10: FFN2 + fused LN2 -> final output (hh read once, no y round-trip)
    hgemm_wide_ln<<<MB, 256, WIDE_SMEM>>>(hh, wh + WOFF_2, b2, xb, g2, be2, out);
}

// round 17
// speedup vs baseline: 1.0057x; 1.0057x over previous
#include <cuda_runtime.h>
#include <cuda_fp16.h>
#include <math_constants.h>
#include <cstdint>

#define N_PTS   92160
#define D_DIM   192
#define BD_DIM  256
#define H_HEADS 8
#define FF_DIM  768
#define S_SETS  2560
#define L_LEN   36
#define M_BOX   256
#define HD_DIM  24
#define SPC     8          // sets per attention CTA

// ---------------- scratch (static device globals; no allocation) ----------------
__device__ float g_proj[N_PTS * D_DIM];
__device__ float g_x[N_PTS * D_DIM];
__device__ float g_k[M_BOX * D_DIM];
__device__ float g_v[M_BOX * D_DIM];
__device__ int   g_fp[N_PTS];

__device__ __half g_qh[N_PTS * D_DIM];
__device__ __half g_ctxh[N_PTS * D_DIM];
__device__ __half g_xh[N_PTS * D_DIM];
__device__ __half g_hh[(size_t)N_PTS * FF_DIM];
__device__ __half g_kh[H_HEADS * M_BOX * 32];      // [h][m][32] padded fp16 K
__device__ __half g_vt[H_HEADS * HD_DIM * M_BOX];  // [h][d][m]  transposed fp16 V
#define WOFF_Q 0
#define WOFF_O 36864
#define WOFF_1 73728
#define WOFF_2 221184
__device__ __half g_wh[368640];

__device__ __forceinline__ void mma16816(float* d, const uint32_t* a, const uint32_t* b) {
    asm volatile(
        "mma.sync.aligned.m16n8k16.row.col.f32.f16.f16.f32 "
        "{%0,%1,%2,%3}, {%4,%5,%6,%7}, {%8,%9}, {%0,%1,%2,%3};\n"
        : "+f"(d[0]), "+f"(d[1]), "+f"(d[2]), "+f"(d[3])
        : "r"(a[0]), "r"(a[1]), "r"(a[2]), "r"(a[3]), "r"(b[0]), "r"(b[1]));
}

__device__ __forceinline__ uint4 add_cvt8(const float* p, const float* q) {
    float4 x0 = *(const float4*)p;
    float4 x1 = *(const float4*)(p + 4);
    float4 y0 = *(const float4*)q;
    float4 y1 = *(const float4*)(q + 4);
    __half2 h0 = __floats2half2_rn(x0.x + y0.x, x0.y + y0.y);
    __half2 h1 = __floats2half2_rn(x0.z + y0.z, x0.w + y0.w);
    __half2 h2 = __floats2half2_rn(x1.x + y1.x, x1.y + y1.y);
    __half2 h3 = __floats2half2_rn(x1.z + y1.z, x1.w + y1.w);
    uint4 r;
    r.x = *(uint32_t*)&h0; r.y = *(uint32_t*)&h1;
    r.z = *(uint32_t*)&h2; r.w = *(uint32_t*)&h3;
    return r;
}

// ================= A-resident fp16 GEMM for K=192: C = A @ W^T + bias =================
#define ARES_SMEM ((128 * 200 + 2 * 64 * 40) * 2)

template<bool RELU, bool OUTH, bool ADDIN, int NTILES>
__global__ __launch_bounds__(256)
void hgemm_ares(const __half* __restrict__ A, const float* __restrict__ Af,
                const float* __restrict__ Af2, const __half* __restrict__ W,
                const float* __restrict__ bias, float* __restrict__ C,
                __half* __restrict__ Ch, int Dout)
{
    extern __shared__ __half dsm[];
    __half* As = dsm;                 // 128 x 200
    __half* Wb0 = dsm + 25600;        // 64 x 40
    __half* Wb1 = dsm + 28160;

    const int tid  = threadIdx.x;
    const int lane = tid & 31;
    const int wid  = tid >> 5;
    const int wm   = wid & 3;
    const int wn   = wid >> 2;
    const int m0   = blockIdx.x * 128;
    const int lr   = lane >> 2;
    const int lc2  = (lane & 3) * 2;

    #pragma unroll
    for (int j = 0; j < 12; j++) {
        const int idx = tid + 256 * j;
        const int r = idx / 24, c8 = (idx % 24) * 8;
        const size_t go = (size_t)(m0 + r) * 192 + c8;
        uint4 v;
        if (ADDIN) v = add_cvt8(Af + go, Af2 + go);
        else       v = *(const uint4*)(A + go);
        *(uint4*)(As + r * 200 + c8) = v;
    }

    const int rw = tid >> 2;
    const int cw = (tid & 3) * 8;
    const int sW = rw * 40 + cw;

    const int NI = NTILES * 6;
    uint4 pw = *(const uint4*)(W + (size_t)rw * 192 + cw);
    *(uint4*)(Wb0 + sW) = pw;

    float acc[2][4][4];

    for (int i = 0; i < NI; ++i) {
        const int nt = i / 6, kc = i % 6;
        __syncthreads();

        if (kc == 0) {
            #pragma unroll
            for (int a = 0; a < 2; a++)
                #pragma unroll
                for (int b = 0; b < 4; b++)
                    #pragma unroll
                    for (int e = 0; e < 4; e++) acc[a][b][e] = 0.f;
        }

        if (i + 1 < NI) {
            const int nt2 = (i + 1) / 6, kc2 = (i + 1) % 6;
            pw = *(const uint4*)(W + (size_t)(nt2 * 64 + rw) * 192 + kc2 * 32 + cw);
        }

        const __half* Ws = (i & 1) ? Wb1 : Wb0;
        const int ca = kc * 32;

        #pragma unroll
        for (int ks = 0; ks < 32; ks += 16) {
            uint32_t af[2][4], bf[4][2];
            #pragma unroll
            for (int a = 0; a < 2; a++) {
                const __half* p = As + (wm * 32 + a * 16 + lr) * 200 + ca + ks + lc2;
                af[a][0] = *(const uint32_t*)(p);
                af[a][1] = *(const uint32_t*)(p + 8 * 200);
                af[a][2] = *(const uint32_t*)(p + 8);
                af[a][3] = *(const uint32_t*)(p + 8 * 200 + 8);
            }
            #pragma unroll
            for (int b = 0; b < 4; b++) {
                const __half* p = Ws + (wn * 32 + b * 8 + lr) * 40 + ks + lc2;
                bf[b][0] = *(const uint32_t*)(p);
                bf[b][1] = *(const uint32_t*)(p + 8);
            }
            #pragma unroll
            for (int a = 0; a < 2; a++)
                #pragma unroll
                for (int b = 0; b < 4; b++)
                    mma16816(acc[a][b], af[a], bf[b]);
        }

        if (kc == 5) {
            const int n0 = nt * 64;
            #pragma unroll
            for (int a = 0; a < 2; a++) {
                const int r = m0 + wm * 32 + a * 16 + lr;
                #pragma unroll
                for (int b = 0; b < 4; b++) {
                    const int cj = n0 + wn * 32 + b * 8 + lc2;
                    const float2 bx = *(const float2*)(bias + cj);
                    float v0 = acc[a][b][0] + bx.x;
                    float v1 = acc[a][b][1] + bx.y;
                    float v2 = acc[a][b][2] + bx.x;
                    float v3 = acc[a][b][3] + bx.y;
                    if (RELU) {
                        v0 = fmaxf(v0, 0.f); v1 = fmaxf(v1, 0.f);
                        v2 = fmaxf(v2, 0.f); v3 = fmaxf(v3, 0.f);
                    }
                    if (OUTH) {
                        *(__half2*)(Ch + (size_t)r       * Dout + cj) = __floats2half2_rn(v0, v1);
                        *(__half2*)(Ch + (size_t)(r + 8) * Dout + cj) = __floats2half2_rn(v2, v3);
                    } else {
                        *(float2*)(C + (size_t)r       * Dout + cj) = make_float2(v0, v1);
                        *(float2*)(C + (size_t)(r + 8) * Dout + cj) = make_float2(v2, v3);
                    }
                }
            }
        }

        if (i + 1 < NI) {
            __half* nb = ((i + 1) & 1) ? Wb1 : Wb0;
            *(uint4*)(nb + sW) = pw;
        }
    }
}

// ================= wide fp16 GEMM + fused LayerNorm: out = LN(X + A@W^T + bias) =================
#define WIDE_SMEM (2 * 320 * 40 * 2)   // 51200 B

__global__ __launch_bounds__(256)
void hgemm_wide_ln(const __half* __restrict__ A, const __half* __restrict__ W,
                   const float* __restrict__ bias, const float* __restrict__ X,
                   const float* __restrict__ gamma, const float* __restrict__ beta,
                   float* __restrict__ Out)
{
    extern __shared__ __half wsm[];
    const int K = FF_DIM;
    const int Dout = D_DIM;

    const int tid  = threadIdx.x;
    const int lane = tid & 31;
    const int wid  = tid >> 5;
    const int wm   = wid & 3;
    const int wn   = wid >> 2;
    const int m0   = blockIdx.x * 128;
    const int lr   = lane >> 2;
    const int lc2  = (lane & 3) * 2;

    const int nT = K >> 5;

    int lrow[5], lcol[5];
    const __half* gptr[5];
    #pragma unroll
    for (int j = 0; j < 5; j++) {
        const int u = tid + 256 * j;
        const int r = u >> 2, c8 = (u & 3) * 8;
        lrow[j] = r; lcol[j] = c8;
        gptr[j] = (r < 128) ? (A + (size_t)(m0 + r) * K + c8)
                            : (W + (size_t)(r - 128) * K + c8);
    }

    uint4 st[5];
    #pragma unroll
    for (int j = 0; j < 5; j++) st[j] = *(const uint4*)(gptr[j]);

    float acc[2][12][4];
    #pragma unroll
    for (int a = 0; a < 2; a++)
        #pragma unroll
        for (int b = 0; b < 12; b++)
            #pragma unroll
            for (int e = 0; e < 4; e++) acc[a][b][e] = 0.f;

    {
        __half* s0 = wsm;
        #pragma unroll
        for (int j = 0; j < 5; j++)
            *(uint4*)(s0 + lrow[j] * 40 + lcol[j]) = st[j];
    }

    for (int t = 0; t < nT; ++t) {
        __syncthreads();

        if (t + 1 < nT) {
            const int off = (t + 1) * 32;
            #pragma unroll
            for (int j = 0; j < 5; j++) st[j] = *(const uint4*)(gptr[j] + off);
        }

        const __half* As = wsm + (t & 1) * (320 * 40);
        const __half* Ws = As + 128 * 40;

        #pragma unroll
        for (int ks = 0; ks < 32; ks += 16) {
            uint32_t af[2][4];
            #pragma unroll
            for (int a = 0; a < 2; a++) {
                const __half* p = As + (wm * 32 + a * 16 + lr) * 40 + ks + lc2;
                af[a][0] = *(const uint32_t*)(p);
                af[a][1] = *(const uint32_t*)(p + 8 * 40);
                af[a][2] = *(const uint32_t*)(p + 8);
                af[a][3] = *(const uint32_t*)(p + 8 * 40 + 8);
            }
            #pragma unroll
            for (int b = 0; b < 12; b++) {
                uint32_t bf[2];
                const __half* p = Ws + (wn * 96 + b * 8 + lr) * 40 + ks + lc2;
                bf[0] = *(const uint32_t*)(p);
                bf[1] = *(const uint32_t*)(p + 8);
                mma16816(acc[0][b], af[0], bf);
                mma16816(acc[1][b], af[1], bf);
            }
        }

        if (t + 1 < nT) {
            __half* nb = wsm + ((t + 1) & 1) * (320 * 40);
            #pragma unroll
            for (int j = 0; j < 5; j++)
                *(uint4*)(nb + lrow[j] * 40 + lcol[j]) = st[j];
        }
    }

    __syncthreads();
    float* redsum = (float*)wsm;
    float* redsq  = redsum + 1024;
    float* stats  = redsq + 1024;

    const int part = wn * 4 + (lane & 3);

    #pragma unroll
    for (int a = 0; a < 2; a++) {
        #pragma unroll
        for (int hf = 0; hf < 2; hf++) {
            const int rl = wm * 32 + a * 16 + hf * 8 + lr;
            const int r  = m0 + rl;
            float s = 0.f, q = 0.f;
            #pragma unroll
            for (int b = 0; b < 12; b++) {
                const int cj = wn * 96 + b * 8 + lc2;
                const float2 bx = *(const float2*)(bias + cj);
                const float2 xv = *(const float2*)(X + (size_t)r * Dout + cj);
                float v0 = acc[a][b][hf*2+0] + bx.x + xv.x;
                float v1 = acc[a][b][hf*2+1] + bx.y + xv.y;
                acc[a][b][hf*2+0] = v0;
                acc[a][b][hf*2+1] = v1;
                s += v0 + v1;
                q += v0 * v0 + v1 * v1;
            }
            redsum[rl * 8 + part] = s;
            redsq [rl * 8 + part] = q;
        }
    }
    __syncthreads();

    if (tid < 128) {
        float s = 0.f, q = 0.f;
        #pragma unroll
        for (int p = 0; p < 8; p++) { s += redsum[tid * 8 + p]; q += redsq[tid * 8 + p]; }
        const float mean = s * (1.0f / D_DIM);
        const float var  = q * (1.0f / D_DIM) - mean * mean;
        stats[tid * 2]     = mean;
        stats[tid * 2 + 1] = rsqrtf(var + 1e-5f);
    }
    __syncthreads();

    #pragma unroll
    for (int a = 0; a < 2; a++) {
        #pragma unroll
        for (int hf = 0; hf < 2; hf++) {
            const int rl = wm * 32 + a * 16 + hf * 8 + lr;
            const int r  = m0 + rl;
            const float mean = stats[rl * 2];
            const float inv  = stats[rl * 2 + 1];
            #pragma unroll
            for (int b = 0; b < 12; b++) {
                const int cj = wn * 96 + b * 8 + lc2;
                const float2 gg = *(const float2*)(gamma + cj);
                const float2 bb2 = *(const float2*)(beta + cj);
                const float v0 = acc[a][b][hf*2+0];
                const float v1 = acc[a][b][hf*2+1];
                *(float2*)(Out + (size_t)r * Dout + cj) =
                    make_float2((v0 - mean) * inv * gg.x + bb2.x,
                                (v1 - mean) * inv * gg.y + bb2.y);
            }
        }
    }
}

// ---------------- combined K/V projection (SIMT fp32), blockIdx.z selects ----------------
#define BM 128
#define BN 64
#define BK 16

__global__ __launch_bounds__(256, 2)
void gemm_kv(const float* __restrict__ boxf, const float* __restrict__ boxp,
             const float* __restrict__ Wk, const float* __restrict__ bk, float* __restrict__ Ck,
             const float* __restrict__ Wv, const float* __restrict__ bv, float* __restrict__ Cv)
{
    const bool isK = (blockIdx.z == 0);
    const float* A   = boxf;
    const float* A2  = isK ? boxp : nullptr;
    const float* W   = isK ? Wk : Wv;
    const float* bias= isK ? bk : bv;
    float* C         = isK ? Ck : Cv;
    const int K = BD_DIM, Dout = D_DIM;

    __shared__ float As[BK][BM + 4];
    __shared__ float Ws[BK][BN + 4];

    const int tid = threadIdx.x;
    const int tx = tid & 15;
    const int ty = tid >> 4;
    const int m0 = blockIdx.y * BM;
    const int n0 = blockIdx.x * BN;

    const int ar = tid >> 2;
    const int ac = (tid & 3) << 2;

    const float* Ap0 = A + (size_t)(m0 + ar)      * K + ac;
    const float* Ap1 = A + (size_t)(m0 + ar + 64) * K + ac;
    const float* Wp  = W + (size_t)(n0 + ar)      * K + ac;

    const int nT = K / BK;

    float4 pa0 = *(const float4*)(Ap0);
    float4 pa1 = *(const float4*)(Ap1);
    float4 pw  = *(const float4*)(Wp);
    if (isK) {
        const float* B0 = A2 + (size_t)(m0 + ar) * K + ac;
        const float* B1 = A2 + (size_t)(m0 + ar + 64) * K + ac;
        float4 q0 = *(const float4*)B0;
        float4 q1 = *(const float4*)B1;
        pa0.x += q0.x; pa0.y += q0.y; pa0.z += q0.z; pa0.w += q0.w;
        pa1.x += q1.x; pa1.y += q1.y; pa1.z += q1.z; pa1.w += q1.w;
    }

    float acc[8][4];
    #pragma unroll
    for (int i = 0; i < 8; i++)
        #pragma unroll
        for (int j = 0; j < 4; j++) acc[i][j] = 0.f;

    for (int t = 0; t < nT; ++t) {
        As[ac+0][ar]    = pa0.x; As[ac+1][ar]    = pa0.y;
        As[ac+2][ar]    = pa0.z; As[ac+3][ar]    = pa0.w;
        As[ac+0][ar+64] = pa1.x; As[ac+1][ar+64] = pa1.y;
        As[ac+2][ar+64] = pa1.z; As[ac+3][ar+64] = pa1.w;
        Ws[ac+0][ar]    = pw.x;  Ws[ac+1][ar]    = pw.y;
        Ws[ac+2][ar]    = pw.z;  Ws[ac+3][ar]    = pw.w;
        __syncthreads();

        if (t + 1 < nT) {
            const int off = (t + 1) * BK;
            pa0 = *(const float4*)(Ap0 + off);
            pa1 = *(const float4*)(Ap1 + off);
            pw  = *(const float4*)(Wp  + off);
            if (isK) {
                const float* B0 = A2 + (size_t)(m0 + ar) * K + ac + off;
                const float* B1 = A2 + (size_t)(m0 + ar + 64) * K + ac + off;
                float4 q0 = *(const float4*)B0;
                float4 q1 = *(const float4*)B1;
                pa0.x += q0.x; pa0.y += q0.y; pa0.z += q0.z; pa0.w += q0.w;
                pa1.x += q1.x; pa1.y += q1.y; pa1.z += q1.z; pa1.w += q1.w;
            }
        }

        #pragma unroll
        for (int k = 0; k < BK; ++k) {
            float a[8], w[4];
            #pragma unroll
            for (int i = 0; i < 8; i++) a[i] = As[k][ty * 8 + i];
            #pragma unroll
            for (int j = 0; j < 4; j++) w[j] = Ws[k][tx * 4 + j];
            #pragma unroll
            for (int i = 0; i < 8; i++)
                #pragma unroll
                for (int j = 0; j < 4; j++) acc[i][j] += a[i] * w[j];
        }
        __syncthreads();
    }

    const float b0 = bias[n0 + tx*4 + 0];
    const float b1 = bias[n0 + tx*4 + 1];
    const float b2 = bias[n0 + tx*4 + 2];
    const float b3 = bias[n0 + tx*4 + 3];
    #pragma unroll
    for (int i = 0; i < 8; i++) {
        float4 o;
        o.x = acc[i][0] + b0; o.y = acc[i][1] + b1;
        o.z = acc[i][2] + b2; o.w = acc[i][3] + b3;
        *(float4*)(C + (size_t)(m0 + ty*8 + i) * Dout + n0 + tx*4) = o;
    }
}

// ---------------- K/V pack ----------------
__global__ void kv_pack(const float* __restrict__ kb, const float* __restrict__ vb,
                        __half* __restrict__ khg, __half* __restrict__ vtg)
{
    const int i = blockIdx.x * 256 + threadIdx.x;
    if (i >= H_HEADS * M_BOX) return;
    const int h = i >> 8, m = i & 255;

    {
        const float4* kp = (const float4*)(kb + (size_t)m * D_DIM + h * HD_DIM);
        __half2 hrow[16];
        #pragma unroll
        for (int j = 0; j < 6; j++) {
            float4 f = kp[j];
            hrow[2*j]   = __floats2half2_rn(f.x, f.y);
            hrow[2*j+1] = __floats2half2_rn(f.z, f.w);
        }
        const __half2 zz = __floats2half2_rn(0.f, 0.f);
        hrow[12] = zz; hrow[13] = zz; hrow[14] = zz; hrow[15] = zz;
        uint4* dst = (uint4*)(khg + ((size_t)h * M_BOX + m) * 32);
        dst[0] = ((const uint4*)hrow)[0];
        dst[1] = ((const uint4*)hrow)[1];
        dst[2] = ((const uint4*)hrow)[2];
        dst[3] = ((const uint4*)hrow)[3];
    }
    {
        const float4* vp = (const float4*)(vb + (size_t)m * D_DIM + h * HD_DIM);
        __half* base = vtg + (size_t)h * HD_DIM * M_BOX + m;
        #pragma unroll
        for (int j = 0; j < 6; j++) {
            float4 g = vp[j];
            base[(4*j+0) * M_BOX] = __float2half(g.x);
            base[(4*j+1) * M_BOX] = __float2half(g.y);
            base[(4*j+2) * M_BOX] = __float2half(g.z);
            base[(4*j+3) * M_BOX] = __float2half(g.w);
        }
    }
}

// ================= tensor-core attention: one CTA per (SPC sets, head) =================
#define AT_QS   0
#define AT_KS   1920
#define AT_VT   12160
#define AT_PS   18496
#define AT_INT  31168
#define ATTN_SMEM (31168 * 2 + (36 + 256) * 4)

__global__ __launch_bounds__(256)
void attn_mma(const __half* __restrict__ qh, const __half* __restrict__ khg,
              const __half* __restrict__ vtg, const int* __restrict__ vinds,
              const int* __restrict__ vcoords, const int* __restrict__ bcoords,
              __half* __restrict__ ctxh)
{
    extern __shared__ __half sm[];
    __half* Qs = sm + AT_QS;
    __half* Ks = sm + AT_KS;
    __half* Vt = sm + AT_VT;
    __half* Ps = sm + AT_PS;
    int* qb = (int*)(sm + AT_INT);
    int* bb = qb + 36;

    const int s0idx = blockIdx.x * SPC, h = blockIdx.y;
    const int t = threadIdx.x, lane = t & 31, wid = t >> 5;
    const int lr = lane >> 2, lc2 = (lane & 3) * 2;

    {
        const uint4* kp = (const uint4*)(khg + ((size_t)h * M_BOX + t) * 32);
        uint4* krow = (uint4*)(Ks + t * 40);
        krow[0] = kp[0];
        krow[1] = kp[1];
        krow[2] = kp[2];
        krow[3] = kp[3];
        bb[t] = bcoords[t * 4];
    }
    {
        const __half* vsrc = vtg + (size_t)h * HD_DIM * M_BOX;
        #pragma unroll
        for (int j = 0; j < 3; j++) {
            const int idx = t + 256 * j;
            const int r = idx >> 5, c = idx & 31;
            *(uint4*)(Vt + r * 264 + c * 8) = *(const uint4*)(vsrc + r * M_BOX + c * 8);
        }
    }

    for (int si = 0; si < SPC; ++si) {
        const int s = s0idx + si;

        {
            const uint4 z4 = make_uint4(0u, 0u, 0u, 0u);
            for (int i = t; i < 36 * 4; i += 256) {
                const int l = i >> 2, c = i & 3;
                uint4 v;
                if (c < 3) v = *(const uint4*)(qh + (size_t)vinds[s * L_LEN + l] * D_DIM + h * HD_DIM + c * 8);
                else       v = z4;
                *(uint4*)(Qs + l * 40 + c * 8) = v;
            }
        }
        if (t < 36) qb[t] = vcoords[(size_t)vinds[s * L_LEN + t] * 4];
        __syncthreads();

        float acc[3][4][4];
        #pragma unroll
        for (int i = 0; i < 3; i++)
            #pragma unroll
            for (int j = 0; j < 4; j++)
                #pragma unroll
                for (int e = 0; e < 4; e++) acc[i][j][e] = 0.f;

        #pragma unroll
        for (int kk = 0; kk < 2; kk++) {
            const int k0 = kk * 16;
            uint32_t af[3][4], bf[4][2];
            #pragma unroll
            for (int i = 0; i < 3; i++) {
                const __half* p = Qs + (i * 16 + lr) * 40 + k0 + lc2;
                af[i][0] = *(const uint32_t*)(p);
                af[i][1] = *(const uint32_t*)(p + 8 * 40);
                af[i][2] = *(const uint32_t*)(p + 8);
                af[i][3] = *(const uint32_t*)(p + 8 * 40 + 8);
            }
            #pragma unroll
            for (int j = 0; j < 4; j++) {
                const __half* p = Ks + (wid * 32 + j * 8 + lr) * 40 + k0 + lc2;
                bf[j][0] = *(const uint32_t*)(p);
                bf[j][1] = *(const uint32_t*)(p + 8);
            }
            #pragma unroll
            for (int i = 0; i < 3; i++)
                #pragma unroll
                for (int j = 0; j < 4; j++)
                    mma16816(acc[i][j], af[i], bf[j]);
        }

        {
            const float scale = 0.20412414523193154f;
            #pragma unroll
            for (int i = 0; i < 3; i++) {
                const int r0 = i * 16 + lr, r1 = r0 + 8;
                const int q0 = (r0 < L_LEN) ? qb[r0] : 0;
                const int q1 = (r1 < L_LEN) ? qb[r1] : 0;
                #pragma unroll
                for (int j = 0; j < 4; j++) {
                    const int c = wid * 32 + j * 8 + lc2;
                    const int b0 = bb[c], b1 = bb[c + 1];
                    if (r0 < L_LEN) {
                        float v0 = (q0 != b0) ? -CUDART_INF_F : acc[i][j][0] * scale;
                        float v1 = (q0 != b1) ? -CUDART_INF_F : acc[i][j][1] * scale;
                        *(__half2*)(Ps + r0 * 264 + c) = __floats2half2_rn(v0, v1);
                    }
                    if (r1 < L_LEN) {
                        float v2 = (q1 != b0) ? -CUDART_INF_F : acc[i][j][2] * scale;
                        float v3 = (q1 != b1) ? -CUDART_INF_F : acc[i][j][3] * scale;
                        *(__half2*)(Ps + r1 * 264 + c) = __floats2half2_rn(v2, v3);
                    }
                }
            }
        }
        __syncthreads();

        for (int l = wid; l < L_LEN; l += 8) {
            __half* row = Ps + l * 264;
            float e[8];
            float mx = -CUDART_INF_F;
            #pragma unroll
            for (int i = 0; i < 8; i++) { e[i] = __half2float(row[lane + 32*i]); mx = fmaxf(mx, e[i]); }
            #pragma unroll
            for (int o = 16; o > 0; o >>= 1) mx = fmaxf(mx, __shfl_xor_sync(0xffffffffu, mx, o));
            float sum = 0.f;
            if (mx > -CUDART_INF_F) {
                #pragma unroll
                for (int i = 0; i < 8; i++) { e[i] = __expf(e[i] - mx); sum += e[i]; }
            } else {
                #pragma unroll
                for (int i = 0; i < 8; i++) e[i] = 0.f;
            }
            #pragma unroll
            for (int o = 16; o > 0; o >>= 1) sum += __shfl_xor_sync(0xffffffffu, sum, o);
            const float inv = sum > 0.f ? 1.0f / sum : 0.f;
            #pragma unroll
            for (int i = 0; i < 8; i++) row[lane + 32*i] = __float2half(e[i] * inv);
        }
        __syncthreads();

        if (wid < 3) {
            const int mt = wid;
            float a2[3][4];
            #pragma unroll
            for (int n = 0; n < 3; n++)
                #pragma unroll
                for (int e = 0; e < 4; e++) a2[n][e] = 0.f;

            #pragma unroll 4
            for (int kt = 0; kt < 16; kt++) {
                uint32_t af[4];
                const __half* pa = Ps + (mt * 16 + lr) * 264 + kt * 16 + lc2;
                af[0] = *(const uint32_t*)(pa);
                af[1] = *(const uint32_t*)(pa + 8 * 264);
                af[2] = *(const uint32_t*)(pa + 8);
                af[3] = *(const uint32_t*)(pa + 8 * 264 + 8);
                #pragma unroll
                for (int nt = 0; nt < 3; nt++) {
                    uint32_t bf[2];
                    const __half* pb = Vt + (nt * 8 + lr) * 264 + kt * 16 + lc2;
                    bf[0] = *(const uint32_t*)(pb);
                    bf[1] = *(const uint32_t*)(pb + 8);
                    mma16816(a2[nt], af, bf);
                }
            }

            const int r0 = mt * 16 + lr, r1 = r0 + 8;
            #pragma unroll
            for (int nt = 0; nt < 3; nt++) {
                const int c = nt * 8 + lc2;
                if (r0 < L_LEN)
                    *(__half2*)(ctxh + ((size_t)s * L_LEN + r0) * D_DIM + h * HD_DIM + c) = __floats2half2_rn(a2[nt][0], a2[nt][1]);
                if (r1 < L_LEN)
                    *(__half2*)(ctxh + ((size_t)s * L_LEN + r1) * D_DIM + h * HD_DIM + c) = __floats2half2_rn(a2[nt][2], a2[nt][3]);
            }
        }
    }
}

// ---------------- first-occurrence scatter index ----------------
__global__ void init_fp_kernel(int* __restrict__ fp)
{
    int i = blockIdx.x * blockDim.x + threadIdx.x;
    if (i < N_PTS) fp[i] = 0x7FFFFFFF;
}

__global__ void fill_fp_kernel(const int* __restrict__ vinds, int* __restrict__ fp)
{
    int p = blockIdx.x * blockDim.x + threadIdx.x;
    if (p < S_SETS * L_LEN) {
        int n = vinds[p];
        if (n >= 0 && n < N_PTS) atomicMin(&fp[n], p);
    }
}

// ---------------- residual + layernorm (warp per row) ----------------
template<bool GATHER, bool OUTH>
__global__ __launch_bounds__(256)
void ln_kernel(const float* __restrict__ a, const float* __restrict__ b,
               const int* __restrict__ fp, const float* __restrict__ gamma,
               const float* __restrict__ beta, float* __restrict__ outp,
               __half* __restrict__ oh)
{
    const int row  = (blockIdx.x * 256 + threadIdx.x) >> 5;
    const int lane = threadIdx.x & 31;
    if (row >= N_PTS) return;

    const float* arow = a + (size_t)row * D_DIM;
    const float* brow;
    if (GATHER) {
        int p = fp[row];
        if (p < 0 || p >= N_PTS) p = row;
        brow = b + (size_t)p * D_DIM;
    } else {
        brow = b + (size_t)row * D_DIM;
    }

    float v[6];
    float s = 0.f;
    #pragma unroll
    for (int i = 0; i < 6; i++) {
        const int idx = lane + 32 * i;
        v[i] = arow[idx] + brow[idx];
        s += v[i];
    }
    #pragma unroll
    for (int o = 16; o > 0; o >>= 1) s += __shfl_xor_sync(0xffffffffu, s, o);
    const float mean = s * (1.0f / D_DIM);

    float q = 0.f;
    #pragma unroll
    for (int i = 0; i < 6; i++) { const float d = v[i] - mean; q += d * d; }
    #pragma unroll
    for (int o = 16; o > 0; o >>= 1) q += __shfl_xor_sync(0xffffffffu, q, o);
    const float inv = rsqrtf(q * (1.0f / D_DIM) + 1e-5f);

    float* orow = outp + (size_t)row * D_DIM;
    #pragma unroll
    for (int i = 0; i < 6; i++) {
        const int idx = lane + 32 * i;
        const float val = (v[i] - mean) * inv * gamma[idx] + beta[idx];
        orow[idx] = val;
        if (OUTH) oh[(size_t)row * D_DIM + idx] = __float2half(val);
    }
}

// ---------------- weight conversion (all four in one launch) ----------------
__global__ void cvt_weights_kernel(const float* __restrict__ Wq, const float* __restrict__ Wo,
                                   const float* __restrict__ W1, const float* __restrict__ W2,
                                   __half* __restrict__ wh)
{
    const int i = blockIdx.x * blockDim.x + threadIdx.x;
    const int n4 = 368640 / 4;
    if (i >= n4) return;
    const int e = i * 4;
    const float* srcp;
    int off;
    if (e < WOFF_O)      { srcp = Wq; off = e - WOFF_Q; }
    else if (e < WOFF_1) { srcp = Wo; off = e - WOFF_O; }
    else if (e < WOFF_2) { srcp = W1; off = e - WOFF_1; }
    else                 { srcp = W2; off = e - WOFF_2; }
    float4 x = *(const float4*)(srcp + off);
    ((__half2*)wh)[2*i]   = __floats2half2_rn(x.x, x.y);
    ((__half2*)wh)[2*i+1] = __floats2half2_rn(x.z, x.w);
}

// ---------------- launch ----------------
extern "C" void kernel_launch(void* const* d_in, const int* in_sizes, int n_in,
                              void* d_out, int out_size)
{
    const float* src     = (const float*)d_in[0];
    const float* pos     = (const float*)d_in[1];
    const float* boxf    = (const float*)d_in[2];
    const float* boxp    = (const float*)d_in[3];
    const int*   vcoords = (const int*)  d_in[4];
    const int*   bcoords = (const int*)  d_in[5];
    const int*   vinds   = (const int*)  d_in[6];
    const float* Wq = (const float*)d_in[7];  const float* bq  = (const float*)d_in[8];
    const float* Wk = (const float*)d_in[9];  const float* bk  = (const float*)d_in[10];
    const float* Wv = (const float*)d_in[11]; const float* bv  = (const float*)d_in[12];
    const float* Wo = (const float*)d_in[13]; const float* bo  = (const float*)d_in[14];
    const float* W1 = (const float*)d_in[15]; const float* b1  = (const float*)d_in[16];
    const float* W2 = (const float*)d_in[17]; const float* b2  = (const float*)d_in[18];
    const float* g1 = (const float*)d_in[19]; const float* be1 = (const float*)d_in[20];
    const float* g2 = (const float*)d_in[21]; const float* be2 = (const float*)d_in[22];
    float* out = (float*)d_out;

    float *projb, *xb, *kb, *vb;
    int* fpb;
    __half *qh, *ctxh, *xh, *hh, *wh, *khg, *vtg;
    cudaGetSymbolAddress((void**)&projb, g_proj);
    cudaGetSymbolAddress((void**)&xb,    g_x);
    cudaGetSymbolAddress((void**)&kb,    g_k);
    cudaGetSymbolAddress((void**)&vb,    g_v);
    cudaGetSymbolAddress((void**)&fpb,   g_fp);
    cudaGetSymbolAddress((void**)&qh,    g_qh);
    cudaGetSymbolAddress((void**)&ctxh,  g_ctxh);
    cudaGetSymbolAddress((void**)&xh,    g_xh);
    cudaGetSymbolAddress((void**)&hh,    g_hh);
    cudaGetSymbolAddress((void**)&wh,    g_wh);
    cudaGetSymbolAddress((void**)&khg,   g_kh);
    cudaGetSymbolAddress((void**)&vtg,   g_vt);

    cudaFuncSetAttribute(attn_mma, cudaFuncAttributeMaxDynamicSharedMemorySize, ATTN_SMEM);
    cudaFuncSetAttribute(hgemm_ares<false, true,  true,  3>,  cudaFuncAttributeMaxDynamicSharedMemorySize, ARES_SMEM);
    cudaFuncSetAttribute(hgemm_ares<false, false, false, 3>,  cudaFuncAttributeMaxDynamicSharedMemorySize, ARES_SMEM);
    cudaFuncSetAttribute(hgemm_ares<true,  true,  false, 12>, cudaFuncAttributeMaxDynamicSharedMemorySize, ARES_SMEM);
    cudaFuncSetAttribute(hgemm_wide_ln, cudaFuncAttributeMaxDynamicSharedMemorySize, WIDE_SMEM);

    const int MB = N_PTS / 128;   // 720

    // 1: weight conversion
    cvt_weights_kernel<<<(368640/4 + 255)/256, 256>>>(Wq, Wo, W1, W2, wh);
    // 2: K/V projections
    gemm_kv<<<dim3(D_DIM/BN, M_BOX/BM, 2), 256>>>(boxf, boxp, Wk, bk, kb, Wv, bv, vb);
    // 3: pack K/V into attention-ready fp16 layouts
    kv_pack<<<(H_HEADS * M_BOX) / 256, 256>>>(kb, vb, khg, vtg);
    // 4: Q = (src + pos) @ Wq^T + bq  (A-resident, fused add+cvt, HALF output)
    hgemm_ares<false, true, true, 3><<<MB, 256, ARES_SMEM>>>(nullptr, src, pos, wh + WOFF_Q, bq, nullptr, qh, D_DIM);
    // 5: tensor-core masked attention (8 sets per CTA)
    attn_mma<<<dim3(S_SETS / SPC, H_HEADS), 256, ATTN_SMEM>>>(qh, khg, vtg, vinds, vcoords, bcoords, ctxh);
    // 6: O projection (A-resident)
    hgemm_ares<false, false, false, 3><<<MB, 256, ARES_SMEM>>>(ctxh, nullptr, nullptr, wh + WOFF_O, bo, projb, nullptr, D_DIM);
    // 7,8: first-occurrence scatter index
    init_fp_kernel<<<N_PTS / 256, 256>>>(fpb);
    fill_fp_kernel<<<(S_SETS * L_LEN) / 256, 256>>>(vinds, fpb);
    // 9: x = LN(src + proj[first_pos]) (+ half copy)
    ln_kernel<true, true><<<N_PTS / 8, 256>>>(src, projb, fpb, g1, be1, xb, xh);
    // 10: FFN1 (A-resident, relu, half out)
    hgemm_ares<true, true, false, 12><<<MB, 256, ARES_SMEM>>>(xh, nullptr, nullptr, wh + WOFF_1, b1, nullptr, hh, FF_DIM);
    // 11: FFN2 + fused LN2 -> final output (hh read once, no y round-trip)
    hgemm_wide_ln<<<MB, 256, WIDE_SMEM>>>(hh, wh + WOFF_2, b2, xb, g2, be2, out);
}